// round 7
// baseline (speedup 1.0000x reference)
#include <cuda_runtime.h>
#include <cuda_bf16.h>
#include <cuda_fp16.h>

// ---------------------------------------------------------------------------
// Retriever: out[e] = relu([q | h_e[h] | r_emb[r] | h_e[t]] @ W1 + b1) @ W2 + b2
//   R'     = rel_embs @ W1[270:398] + (q @ W1[0:128] + b1)    (500 x 128, fp16)
//   AB     = h_e @ [W1[128:270] | W1[398:540]]                (N x 256, fp16)
//            split-bf16 mma.sync GEMM over K=128 (emb cols) on a side stream,
//            overlapped with the DDE atomic chain; then a rank-14 fp32 fixup
//            adds the topic/DDE columns' contribution.
//   out[e] = W2 . relu(AB[h,0:128] + AB[t,128:256] + R'[r]) + b2
// NOTE: harness compiles PTX for plain sm_100 -> tcgen05 is NOT available;
// tensor work goes through mma.sync (verified to compile+run in R4/R5).
// ---------------------------------------------------------------------------

#define E_MAX 500000
#define N_MAX 100000
#define HE_W  144      // row pitch in bf16 for h_e / Wcat

__device__ int    g_hh[E_MAX];
__device__ int    g_tt[E_MAX];
__device__ int    g_rr[E_MAX];
__device__ float4 g_f0[N_MAX];                         // fwd r1 sums + cnt_t in .z
__device__ float4 g_r0[N_MAX];                         // rev r1 sums + cnt_h in .z
__device__ float2 g_f1[N_MAX], g_f2[N_MAX];            // fwd rounds 2,3 sums
__device__ float2 g_r1[N_MAX], g_r2[N_MAX];            // rev rounds 2,3 sums
__device__ __nv_bfloat16 g_heh[(size_t)N_MAX * HE_W];  // h_e hi (cols 0..127)
__device__ __nv_bfloat16 g_hel[(size_t)N_MAX * HE_W];  // h_e lo
__device__ __nv_bfloat16 g_wh[256 * HE_W];             // Wcat hi, [n][k]
__device__ __nv_bfloat16 g_wl[256 * HE_W];             // Wcat lo
__device__ uint4  g_ab[(size_t)N_MAX * 32];            // AB  [N,256] fp16
__device__ uint4  g_rp[512 * 16];                      // R' [NREL,128] fp16

__device__ __forceinline__ unsigned pack2(__nv_bfloat16 x, __nv_bfloat16 y) {
    __nv_bfloat162 t = __halves2bfloat162(x, y);
    return *(unsigned*)&t;
}
__device__ __forceinline__ void split1(float v, __nv_bfloat16& h, __nv_bfloat16& l) {
    h = __float2bfloat16(v);
    l = __float2bfloat16(v - __bfloat162float(h));
}
__device__ __forceinline__ float2 h22f(unsigned u) {
    return __half22float2(*(__half2*)&u);
}
__device__ __forceinline__ void red2(float2* p, float x, float y) {
    asm volatile("red.global.add.v2.f32 [%0], {%1, %2};"
                 :: "l"(p), "f"(x), "f"(y) : "memory");
}
__device__ __forceinline__ void red4(float4* p, float x, float y, float z, float w) {
    asm volatile("red.global.add.v4.f32 [%0], {%1, %2, %3, %4};"
                 :: "l"(p), "f"(x), "f"(y), "f"(z), "f"(w) : "memory");
}

// ---------------- build h_e hi/lo cols 0..127 + zero DDE state ----------------
__global__ void k_fill(const float* __restrict__ ent, const float* __restrict__ nont,
                       int Nn, int Ntext) {
    int i = blockIdx.x * 256 + threadIdx.x;
    if (i >= Nn * 32) return;
    int node = i >> 5, c4 = i & 31;
    const float* src = (node < Ntext) ? (ent + (size_t)node * 128 + c4 * 4)
                                      : (nont + c4 * 4);
    float4 v = *(const float4*)src;
    __nv_bfloat16 hx, hy, hz, hw, lx, ly, lz, lw;
    split1(v.x, hx, lx); split1(v.y, hy, ly);
    split1(v.z, hz, lz); split1(v.w, hw, lw);
    size_t off = (size_t)node * HE_W + c4 * 4;
    *(uint2*)(g_heh + off) = make_uint2(pack2(hx, hy), pack2(hz, hw));
    *(uint2*)(g_hel + off) = make_uint2(pack2(lx, ly), pack2(lz, lw));
    if (c4 == 0) {   // piggyback: zero DDE accumulators
        g_f0[node] = make_float4(0.f, 0.f, 0.f, 0.f);
        g_r0[node] = make_float4(0.f, 0.f, 0.f, 0.f);
        g_f1[node] = make_float2(0.f, 0.f);
        g_f2[node] = make_float2(0.f, 0.f);
        g_r1[node] = make_float2(0.f, 0.f);
        g_r2[node] = make_float2(0.f, 0.f);
    }
}

// ------- ids -> int32 (+dtype detect) + DDE round 0 (sums + counts, red.v4) ---
__global__ void k_convert(const void* ph, const void* pr, const void* pt,
                          const float* __restrict__ topic, int E) {
    __shared__ int s64;
    if (threadIdx.x == 0) {
        // int64 vs int32: int64 view of int32 r-id buffer is >= 2^32 a.s.
        const long long* p = (const long long*)ph;
        const long long* qq = (const long long*)pr;
        int ok = 1;
        for (int i = 0; i < 8; i++) {
            long long v = p[i];  if (v < 0 || v >= 1000000) ok = 0;
            long long w = qq[i]; if (w < 0 || w >= 1000000) ok = 0;
        }
        s64 = ok;
    }
    __syncthreads();
    int e = blockIdx.x * 256 + threadIdx.x;
    if (e >= E) return;
    int h, r, t;
    if (s64) {
        h = (int)((const long long*)ph)[e];
        r = (int)((const long long*)pr)[e];
        t = (int)((const long long*)pt)[e];
    } else {
        h = ((const int*)ph)[e];
        r = ((const int*)pr)[e];
        t = ((const int*)pt)[e];
    }
    g_hh[e] = h; g_rr[e] = r; g_tt[e] = t;
    const float2* tp2 = (const float2*)topic;
    float2 th = __ldg(tp2 + h);
    float2 tt = __ldg(tp2 + t);
    red4(&g_f0[t], th.x, th.y, 1.0f, 0.f);   // fwd: h -> t  (+count)
    red4(&g_r0[h], tt.x, tt.y, 1.0f, 0.f);   // rev: t -> h  (+count)
}

// ------- DDE scatter round rd (1 or 2): normalize prev sums, red.v2 ------------
__global__ void k_scat(int rd, int E) {
    int e = blockIdx.x * 256 + threadIdx.x;
    if (e >= E) return;
    int h = g_hh[e], t = g_tt[e];
    if (rd == 1) {
        float4 f0h = __ldg(&g_f0[h]);
        float4 r0t = __ldg(&g_r0[t]);
        float ict = 1.0f / fmaxf(f0h.z, 1.0f);
        float ich = 1.0f / fmaxf(r0t.z, 1.0f);
        red2(&g_f1[t], f0h.x * ict, f0h.y * ict);
        red2(&g_r1[h], r0t.x * ich, r0t.y * ich);
    } else {
        float cth = __ldg(((const float*)g_f0) + 4 * (size_t)h + 2);
        float cht = __ldg(((const float*)g_r0) + 4 * (size_t)t + 2);
        float2 f1h = __ldg(&g_f1[h]);
        float2 r1t = __ldg(&g_r1[t]);
        float ict = 1.0f / fmaxf(cth, 1.0f);
        float ich = 1.0f / fmaxf(cht, 1.0f);
        red2(&g_f2[t], f1h.x * ict, f1h.y * ict);
        red2(&g_r2[h], r1t.x * ich, r1t.y * ich);
    }
}

// ------- prep: Wcat split-bf16 [n][k] | R' = rel@W1_r + (q@W1_q + b1), fp16 ----
__global__ void k_prep(const float* __restrict__ W1, const float* __restrict__ rel,
                       const float* __restrict__ q, const float* __restrict__ b1,
                       int NREL) {
    int bid = blockIdx.x;
    int tid = threadIdx.x;
    if (bid < 144) {                       // Wcat: 256 elements of the [n][k] array
        int idx = bid * 256 + tid;
        int n = idx / 144, k = idx % 144;
        float v = 0.f;
        if (k < 142) v = (n < 128) ? W1[(128 + k) * 128 + n]
                                   : W1[(398 + k) * 128 + (n - 128)];
        __nv_bfloat16 h, l;
        split1(v, h, l);
        g_wh[idx] = h;
        g_wl[idx] = l;
    } else {                               // two relations per block
        __shared__ float rs[256];
        __shared__ float qs[128];
        int r = (bid - 144) * 2 + (tid >> 7);
        int j = tid & 127;
        int base = tid & ~127;
        if (tid < 128) qs[tid] = q[tid];
        rs[tid] = (r < NREL) ? rel[(size_t)r * 128 + j] : 0.f;
        __syncthreads();
        if (r < NREL) {
            float accc = b1[j];
#pragma unroll 8
            for (int k = 0; k < 128; k++) accc += qs[k] * __ldg(&W1[k * 128 + j]);
            float accr = 0.f;
#pragma unroll 8
            for (int k = 0; k < 128; k++) accr += rs[base + k] * __ldg(&W1[(270 + k) * 128 + j]);
            ((__half*)g_rp)[(size_t)r * 128 + j] = __float2half(accc + accr);
        }
    }
}

// ---------------------------------------------------------------------------
// Main GEMM (K=128, emb cols only): AB = h_e[:,0:128] @ Wcat[0:128,:],
// split-bf16 mma.sync (3 products, fp32 accum). Block 128x128, 8 warps,
// warp tile 64x32, BK=16, cp.async double-buffered. Runs on a side stream
// concurrently with the DDE chain (needs only k_fill + k_prep).
// ---------------------------------------------------------------------------
#define APITCH 24   // smem row pitch in bf16 (48B -> conflict-free ldmatrix)

__device__ __forceinline__ void ldsm4(unsigned* r, unsigned a) {
    asm volatile("ldmatrix.sync.aligned.m8n8.x4.shared.b16 {%0,%1,%2,%3}, [%4];"
                 : "=r"(r[0]), "=r"(r[1]), "=r"(r[2]), "=r"(r[3]) : "r"(a));
}
__device__ __forceinline__ void mma_bf16(float* d, const unsigned* a, unsigned b0, unsigned b1) {
    asm volatile("mma.sync.aligned.m16n8k16.row.col.f32.bf16.bf16.f32 "
                 "{%0,%1,%2,%3}, {%4,%5,%6,%7}, {%8,%9}, {%0,%1,%2,%3};"
                 : "+f"(d[0]), "+f"(d[1]), "+f"(d[2]), "+f"(d[3])
                 : "r"(a[0]), "r"(a[1]), "r"(a[2]), "r"(a[3]), "r"(b0), "r"(b1));
}
__device__ __forceinline__ void cp16(unsigned dst, const void* src) {
    asm volatile("cp.async.ca.shared.global [%0], [%1], 16;" :: "r"(dst), "l"(src));
}

__global__ __launch_bounds__(256) void k_gemm(int Nn) {
    // smem: [sel(A/B)][buf][arr(hi/lo)][128*APITCH] bf16 = 48 KB
    __shared__ __align__(16) __nv_bfloat16 sm[8 * 128 * APITCH];
    unsigned smb = (unsigned)__cvta_generic_to_shared(sm);
    int tid = threadIdx.x;
    int m0 = blockIdx.x * 128, n0 = blockIdx.y * 128;
    int wid = tid >> 5, lane = tid & 31;
    int wm = (wid >> 2) * 64, wn = (wid & 3) * 32;

    // staging map: 4 slots/thread. slots 0,1 -> A ; 2,3 -> B.
    const __nv_bfloat16* gbase[4];
    unsigned dstoff[4];   // smem byte offset excluding buf
#pragma unroll
    for (int s = 0; s < 4; s++) {
        int idx = tid + 256 * s;
        int sel = idx >> 9;            // 0 = A, 1 = B
        int rem = idx & 511;
        int row = rem >> 2, qq = rem & 3;
        int arr = qq >> 1, half = qq & 1;
        if (sel == 0) {
            int gr = m0 + row; if (gr >= Nn) gr = Nn - 1;
            gbase[s] = (arr ? g_hel : g_heh) + (size_t)gr * HE_W + half * 8;
        } else {
            gbase[s] = (arr ? g_wl : g_wh) + (size_t)(n0 + row) * HE_W + half * 8;
        }
        dstoff[s] = ((unsigned)(sel * 4 + arr) * 3072 + row * APITCH + half * 8) * 2;
    }
    const unsigned bufstride = 2u * 3072u * 2u;   // bytes between buf0/buf1 regions

    float acc[4][4][4];
#pragma unroll
    for (int i = 0; i < 4; i++)
#pragma unroll
        for (int j = 0; j < 4; j++)
#pragma unroll
            for (int k = 0; k < 4; k++) acc[i][j][k] = 0.f;

    int ldrow = lane & 15, ldk = (lane >> 4) * 8;

    // ---- prologue: stage tile 0 into buf 0 ----
#pragma unroll
    for (int s = 0; s < 4; s++) cp16(smb + dstoff[s], gbase[s]);
    asm volatile("cp.async.commit_group;");

    for (int it = 0; it < 8; ++it) {
        int buf = it & 1;
        asm volatile("cp.async.wait_group 0;");
        __syncthreads();

        if (it < 7) {
            unsigned bofs = (buf ^ 1) * bufstride;
#pragma unroll
            for (int s = 0; s < 4; s++)
                cp16(smb + bofs + dstoff[s], gbase[s] + (it + 1) * 16);
            asm volatile("cp.async.commit_group;");
        }

        // ---- fragments from buf ----
        unsigned aoff = buf * bufstride;
        unsigned Ah[4][4], Al[4][4], Bh[2][4], Bl[2][4];
#pragma unroll
        for (int mf = 0; mf < 4; mf++) {
            unsigned r = (wm + mf * 16 + ldrow) * APITCH + ldk;
            ldsm4(Ah[mf], smb + aoff + (0 * 3072 + r) * 2);
            ldsm4(Al[mf], smb + aoff + (1 * 3072 + r) * 2);
        }
#pragma unroll
        for (int nh = 0; nh < 2; nh++) {
            unsigned r = (wn + nh * 16 + ldrow) * APITCH + ldk;
            ldsm4(Bh[nh], smb + aoff + (4 * 3072 + r) * 2);
            ldsm4(Bl[nh], smb + aoff + (5 * 3072 + r) * 2);
        }
#pragma unroll
        for (int mf = 0; mf < 4; mf++)
#pragma unroll
            for (int nf = 0; nf < 4; nf++) {
                int nh = nf >> 1, sel = nf & 1;
                unsigned bh0 = Bh[nh][sel], bh1 = Bh[nh][sel + 2];
                unsigned bl0 = Bl[nh][sel], bl1 = Bl[nh][sel + 2];
                mma_bf16(acc[mf][nf], Ah[mf], bh0, bh1);   // hi*hi
                mma_bf16(acc[mf][nf], Ah[mf], bl0, bl1);   // hi*lo
                mma_bf16(acc[mf][nf], Al[mf], bh0, bh1);   // lo*hi
            }
        if (it < 7) __syncthreads();
    }

    // ---- epilogue: fp32 acc -> fp16 AB ----
    int g = lane >> 2, tg = lane & 3;
    unsigned* outw = (unsigned*)g_ab;
#pragma unroll
    for (int mf = 0; mf < 4; mf++)
#pragma unroll
        for (int nf = 0; nf < 4; nf++) {
            int col = n0 + wn + nf * 8 + 2 * tg;
            int r0 = m0 + wm + mf * 16 + g;
            if (r0 < Nn) {
                __half2 p = __floats2half2_rn(acc[mf][nf][0], acc[mf][nf][1]);
                outw[(size_t)r0 * 128 + (col >> 1)] = *(unsigned*)&p;
            }
            int r1 = r0 + 8;
            if (r1 < Nn) {
                __half2 p = __floats2half2_rn(acc[mf][nf][2], acc[mf][nf][3]);
                outw[(size_t)r1 * 128 + (col >> 1)] = *(unsigned*)&p;
            }
        }
}

// ---------------------------------------------------------------------------
// Rank-14 fixup: AB[i,:] += dde_feats(i)[14] @ Wdde[14,256], fp32 math,
// fp16 read-modify-write. Wdde = W1 rows 256..269 (n<128) / 526..539 (n>=128).
// One warp per node; lane handles 8 consecutive columns (one uint4 of AB).
// ---------------------------------------------------------------------------
__global__ __launch_bounds__(256) void k_dde(const float* __restrict__ W1,
                                             const float* __restrict__ topic, int Nn) {
    __shared__ float Ws[14][256];
    int tid = threadIdx.x;
    for (int i = tid; i < 14 * 256; i += 256) {
        int k = i >> 8, n = i & 255;
        Ws[k][n] = (n < 128) ? __ldg(&W1[(256 + k) * 128 + n])
                             : __ldg(&W1[(526 + k) * 128 + (n - 128)]);
    }
    __syncthreads();
    int node = (blockIdx.x * 256 + tid) >> 5;
    int lane = tid & 31;
    if (node >= Nn) return;

    float2 tp = __ldg(((const float2*)topic) + node);
    float4 f0 = __ldg(&g_f0[node]);
    float2 f1 = __ldg(&g_f1[node]), f2 = __ldg(&g_f2[node]);
    float4 r0 = __ldg(&g_r0[node]);
    float2 r1 = __ldg(&g_r1[node]), r2 = __ldg(&g_r2[node]);
    float ict = 1.0f / fmaxf(f0.z, 1.0f);
    float ich = 1.0f / fmaxf(r0.z, 1.0f);
    float d[14];
    d[0] = tp.x;       d[1] = tp.y;
    d[2] = f0.x * ict; d[3] = f0.y * ict;
    d[4] = f1.x * ict; d[5] = f1.y * ict;
    d[6] = f2.x * ict; d[7] = f2.y * ict;
    d[8] = r0.x * ich; d[9] = r0.y * ich;
    d[10] = r1.x * ich; d[11] = r1.y * ich;
    d[12] = r2.x * ich; d[13] = r2.y * ich;

    size_t abi = (size_t)node * 32 + lane;
    uint4 ab = g_ab[abi];
    float2 p0 = h22f(ab.x), p1 = h22f(ab.y), p2 = h22f(ab.z), p3 = h22f(ab.w);
    float acc[8] = {p0.x, p0.y, p1.x, p1.y, p2.x, p2.y, p3.x, p3.y};
    int col = lane * 8;
#pragma unroll
    for (int k = 0; k < 14; k++) {
        float dk = d[k];
        const float* w = &Ws[k][col];
#pragma unroll
        for (int j = 0; j < 8; j++) acc[j] += dk * w[j];
    }
    __half2 q0 = __floats2half2_rn(acc[0], acc[1]);
    __half2 q1 = __floats2half2_rn(acc[2], acc[3]);
    __half2 q2 = __floats2half2_rn(acc[4], acc[5]);
    __half2 q3 = __floats2half2_rn(acc[6], acc[7]);
    g_ab[abi] = make_uint4(*(unsigned*)&q0, *(unsigned*)&q1,
                           *(unsigned*)&q2, *(unsigned*)&q3);
}

// -------- edge stage: 16 lanes per edge, uint4 (LDG.128) gathers --------------
__global__ __launch_bounds__(256) void k_edge(float* __restrict__ out,
                                              const float4* __restrict__ w2,
                                              const float* __restrict__ b2, int E) {
    int gt = blockIdx.x * 256 + threadIdx.x;
    int e = gt >> 4, sub = gt & 15;
    bool valid = (e < E);
    if (e >= E) e = E - 1;
    int h = g_hh[e], t = g_tt[e], r = g_rr[e];
    uint4 ua = __ldg(&g_ab[(size_t)h * 32 + sub]);        // cols 8s..8s+7 of A
    uint4 ub = __ldg(&g_ab[(size_t)t * 32 + 16 + sub]);   // cols 8s..8s+7 of B
    uint4 ur = __ldg(&g_rp[(size_t)r * 16 + sub]);        // R' (c, b1 folded in)
    float4 w0 = __ldg(&w2[2 * sub]);
    float4 w1 = __ldg(&w2[2 * sub + 1]);
    float2 a0 = h22f(ua.x), a1 = h22f(ua.y), a2 = h22f(ua.z), a3 = h22f(ua.w);
    float2 b0 = h22f(ub.x), b1 = h22f(ub.y), b2v = h22f(ub.z), b3 = h22f(ub.w);
    float2 r0 = h22f(ur.x), r1 = h22f(ur.y), r2 = h22f(ur.z), r3 = h22f(ur.w);
    float s = fmaxf(a0.x + b0.x + r0.x, 0.f) * w0.x
            + fmaxf(a0.y + b0.y + r0.y, 0.f) * w0.y
            + fmaxf(a1.x + b1.x + r1.x, 0.f) * w0.z
            + fmaxf(a1.y + b1.y + r1.y, 0.f) * w0.w
            + fmaxf(a2.x + b2v.x + r2.x, 0.f) * w1.x
            + fmaxf(a2.y + b2v.y + r2.y, 0.f) * w1.y
            + fmaxf(a3.x + b3.x + r3.x, 0.f) * w1.z
            + fmaxf(a3.y + b3.y + r3.y, 0.f) * w1.w;
    s += __shfl_xor_sync(0xffffffff, s, 8);
    s += __shfl_xor_sync(0xffffffff, s, 4);
    s += __shfl_xor_sync(0xffffffff, s, 2);
    s += __shfl_xor_sync(0xffffffff, s, 1);
    if (valid && sub == 0) out[e] = s + __ldg(b2);
}

// ---------------------------------------------------------------------------
// Streams/events created in a static initializer (before harness checkpoints).
struct HxRes {
    cudaStream_t s1, s2;
    cudaEvent_t e0, e1, e2;
    HxRes() {
        cudaStreamCreateWithFlags(&s1, cudaStreamNonBlocking);
        cudaStreamCreateWithFlags(&s2, cudaStreamNonBlocking);
        cudaEventCreateWithFlags(&e0, cudaEventDisableTiming);
        cudaEventCreateWithFlags(&e1, cudaEventDisableTiming);
        cudaEventCreateWithFlags(&e2, cudaEventDisableTiming);
    }
};
static HxRes hx;

extern "C" void kernel_launch(void* const* d_in, const int* in_sizes, int n_in,
                              void* d_out, int out_size) {
    int off = (n_in >= 13) ? 0 : -1;   // robust to scalar input being dropped
    const void*  ph    = d_in[0];
    const void*  pr    = d_in[1];
    const void*  pt    = d_in[2];
    const float* q     = (const float*)d_in[3];
    const float* ent   = (const float*)d_in[4];
    const float* rel   = (const float*)d_in[6 + off];
    const float* topic = (const float*)d_in[7 + off];
    const float* nont  = (const float*)d_in[8 + off];
    const float* W1    = (const float*)d_in[9 + off];
    const float* b1    = (const float*)d_in[10 + off];
    const float* W2    = (const float*)d_in[11 + off];
    const float* b2    = (const float*)d_in[12 + off];

    int E     = in_sizes[0];
    int Ntext = in_sizes[4] / 128;
    int NREL  = in_sizes[6 + off] / 128;
    int Nn    = in_sizes[7 + off] / 2;
    if (E > E_MAX) E = E_MAX;
    if (Nn > N_MAX) Nn = N_MAX;
    if (NREL > 512) NREL = 512;

    int gE = (E + 255) / 256;
    int nrelb = (NREL + 1) / 2;

    // fork: fill + (prep -> main GEMM) on side streams, DDE chain on main
    cudaEventRecord(hx.e0, 0);
    cudaStreamWaitEvent(hx.s1, hx.e0, 0);
    cudaStreamWaitEvent(hx.s2, hx.e0, 0);

    k_fill<<<(Nn * 32 + 255) / 256, 256, 0, hx.s1>>>(ent, nont, Nn, Ntext);
    k_prep<<<144 + nrelb, 256, 0, hx.s2>>>(W1, rel, q, b1, NREL);
    cudaEventRecord(hx.e2, hx.s2);

    // main GEMM on s1 (needs fill [same stream] + prep [event]); overlaps DDE
    cudaStreamWaitEvent(hx.s1, hx.e2, 0);
    dim3 ggrid((Nn + 127) / 128, 2);
    k_gemm<<<ggrid, 256, 0, hx.s1>>>(Nn);
    cudaEventRecord(hx.e1, hx.s1);

    // DDE atomic chain on the main stream (concurrent with the GEMM)
    k_convert<<<gE, 256>>>(ph, pr, pt, topic, E);   // ids + DDE round 0 + counts
    k_scat<<<gE, 256>>>(1, E);                      // DDE round 1 -> 2
    k_scat<<<gE, 256>>>(2, E);                      // DDE round 2 -> 3

    // join: fixup needs DDE (this stream) + main GEMM (event)
    cudaStreamWaitEvent(0, hx.e1, 0);
    k_dde<<<(Nn * 32 + 255) / 256, 256>>>(W1, topic, Nn);

    k_edge<<<(E * 16 + 255) / 256, 256>>>((float*)d_out, (const float4*)W2, b2, E);
}

// round 8
// speedup vs baseline: 1.9282x; 1.9282x over previous
#include <cuda_runtime.h>
#include <cuda_bf16.h>
#include <cuda_fp16.h>

// ---------------------------------------------------------------------------
// Retriever: out[e] = relu([q | h_e[h] | r_emb[r] | h_e[t]] @ W1 + b1) @ W2 + b2
//   R'     = rel_embs @ W1[270:398] + (q @ W1[0:128] + b1)    (500 x 128, fp16)
//   AB     = h_e @ [W1[128:270] | W1[398:540]]                (N x 256, fp16)
//            single-product fp16 mma.sync GEMM (fp32 accum); DDE columns
//            synthesized into SMEM inside the GEMM (R5 skeleton).
//   out[e] = W2 . relu(AB[h,0:128] + AB[t,128:256] + R'[r]) + b2
// NOTES: harness PTX targets plain sm_100 -> tcgen05 unavailable; mma.sync only.
//        R7 lesson: do NOT overlap the GEMM with the DDE atomic chain (L2
//        contention regressed 207->311); serial R5 ordering restored.
// ---------------------------------------------------------------------------

#define E_MAX 500000
#define N_MAX 100000
#define HE_W  144      // row pitch in fp16 for h_e / Wcat (142 used, 2 zero)

__device__ int    g_hh[E_MAX];
__device__ int    g_tt[E_MAX];
__device__ int    g_rr[E_MAX];
__device__ float4 g_f0[N_MAX];                         // fwd r1 sums + cnt_t in .z
__device__ float4 g_r0[N_MAX];                         // rev r1 sums + cnt_h in .z
__device__ float2 g_f1[N_MAX], g_f2[N_MAX];            // fwd rounds 2,3 sums
__device__ float2 g_r1[N_MAX], g_r2[N_MAX];            // rev rounds 2,3 sums
__device__ __half g_hef[(size_t)N_MAX * HE_W];         // h_e fp16 (cols 0..127)
__device__ __half g_wf[256 * HE_W];                    // Wcat fp16, [n][k]
__device__ uint4  g_ab[(size_t)N_MAX * 32];            // AB  [N,256] fp16
__device__ uint4  g_rp[512 * 16];                      // R' [NREL,128] fp16

__device__ __forceinline__ unsigned packh2(float x, float y) {
    __half2 t = __floats2half2_rn(x, y);
    return *(unsigned*)&t;
}
__device__ __forceinline__ float2 h22f(unsigned u) {
    return __half22float2(*(__half2*)&u);
}
__device__ __forceinline__ void red2(float2* p, float x, float y) {
    asm volatile("red.global.add.v2.f32 [%0], {%1, %2};"
                 :: "l"(p), "f"(x), "f"(y) : "memory");
}
__device__ __forceinline__ void red4(float4* p, float x, float y, float z, float w) {
    asm volatile("red.global.add.v4.f32 [%0], {%1, %2, %3, %4};"
                 :: "l"(p), "f"(x), "f"(y), "f"(z), "f"(w) : "memory");
}

// ---------------- build h_e fp16 cols 0..127 + zero DDE state ----------------
__global__ void k_fill(const float* __restrict__ ent, const float* __restrict__ nont,
                       int Nn, int Ntext) {
    int i = blockIdx.x * 256 + threadIdx.x;
    if (i >= Nn * 32) return;
    int node = i >> 5, c4 = i & 31;
    const float* src = (node < Ntext) ? (ent + (size_t)node * 128 + c4 * 4)
                                      : (nont + c4 * 4);
    float4 v = *(const float4*)src;
    *(uint2*)(g_hef + (size_t)node * HE_W + c4 * 4) =
        make_uint2(packh2(v.x, v.y), packh2(v.z, v.w));
    if (c4 == 0) {   // piggyback: zero DDE accumulators
        g_f0[node] = make_float4(0.f, 0.f, 0.f, 0.f);
        g_r0[node] = make_float4(0.f, 0.f, 0.f, 0.f);
        g_f1[node] = make_float2(0.f, 0.f);
        g_f2[node] = make_float2(0.f, 0.f);
        g_r1[node] = make_float2(0.f, 0.f);
        g_r2[node] = make_float2(0.f, 0.f);
    }
}

// ------- ids -> int32 (+dtype detect) + DDE round 0 (sums + counts, red.v4) ---
__global__ void k_convert(const void* ph, const void* pr, const void* pt,
                          const float* __restrict__ topic, int E) {
    __shared__ int s64;
    if (threadIdx.x == 0) {
        // int64 vs int32: int64 view of int32 r-id buffer is >= 2^32 a.s.
        const long long* p = (const long long*)ph;
        const long long* qq = (const long long*)pr;
        int ok = 1;
        for (int i = 0; i < 8; i++) {
            long long v = p[i];  if (v < 0 || v >= 1000000) ok = 0;
            long long w = qq[i]; if (w < 0 || w >= 1000000) ok = 0;
        }
        s64 = ok;
    }
    __syncthreads();
    int e = blockIdx.x * 256 + threadIdx.x;
    if (e >= E) return;
    int h, r, t;
    if (s64) {
        h = (int)((const long long*)ph)[e];
        r = (int)((const long long*)pr)[e];
        t = (int)((const long long*)pt)[e];
    } else {
        h = ((const int*)ph)[e];
        r = ((const int*)pr)[e];
        t = ((const int*)pt)[e];
    }
    g_hh[e] = h; g_rr[e] = r; g_tt[e] = t;
    const float2* tp2 = (const float2*)topic;
    float2 th = __ldg(tp2 + h);
    float2 tt = __ldg(tp2 + t);
    red4(&g_f0[t], th.x, th.y, 1.0f, 0.f);   // fwd: h -> t  (+count)
    red4(&g_r0[h], tt.x, tt.y, 1.0f, 0.f);   // rev: t -> h  (+count)
}

// ------- DDE scatter round rd (1 or 2): normalize prev sums, red.v2 ------------
__global__ void k_scat(int rd, int E) {
    int e = blockIdx.x * 256 + threadIdx.x;
    if (e >= E) return;
    int h = g_hh[e], t = g_tt[e];
    if (rd == 1) {
        float4 f0h = __ldg(&g_f0[h]);
        float4 r0t = __ldg(&g_r0[t]);
        float ict = 1.0f / fmaxf(f0h.z, 1.0f);
        float ich = 1.0f / fmaxf(r0t.z, 1.0f);
        red2(&g_f1[t], f0h.x * ict, f0h.y * ict);
        red2(&g_r1[h], r0t.x * ich, r0t.y * ich);
    } else {
        float cth = __ldg(((const float*)g_f0) + 4 * (size_t)h + 2);
        float cht = __ldg(((const float*)g_r0) + 4 * (size_t)t + 2);
        float2 f1h = __ldg(&g_f1[h]);
        float2 r1t = __ldg(&g_r1[t]);
        float ict = 1.0f / fmaxf(cth, 1.0f);
        float ich = 1.0f / fmaxf(cht, 1.0f);
        red2(&g_f2[t], f1h.x * ict, f1h.y * ict);
        red2(&g_r2[h], r1t.x * ich, r1t.y * ich);
    }
}

// ------- prep: Wcat fp16 [n][k] | R' = rel@W1_r + (q@W1_q + b1), fp16 ----------
__global__ void k_prep(const float* __restrict__ W1, const float* __restrict__ rel,
                       const float* __restrict__ q, const float* __restrict__ b1,
                       int NREL) {
    int bid = blockIdx.x;
    int tid = threadIdx.x;
    if (bid < 144) {                       // Wcat: 256 elements of the [n][k] array
        int idx = bid * 256 + tid;
        int n = idx / 144, k = idx % 144;
        float v = 0.f;
        if (k < 142) v = (n < 128) ? W1[(128 + k) * 128 + n]
                                   : W1[(398 + k) * 128 + (n - 128)];
        g_wf[idx] = __float2half(v);
    } else {                               // two relations per block
        __shared__ float rs[256];
        __shared__ float qs[128];
        int r = (bid - 144) * 2 + (tid >> 7);
        int j = tid & 127;
        int base = tid & ~127;
        if (tid < 128) qs[tid] = q[tid];
        rs[tid] = (r < NREL) ? rel[(size_t)r * 128 + j] : 0.f;
        __syncthreads();
        if (r < NREL) {
            float accc = b1[j];
#pragma unroll 8
            for (int k = 0; k < 128; k++) accc += qs[k] * __ldg(&W1[k * 128 + j]);
            float accr = 0.f;
#pragma unroll 8
            for (int k = 0; k < 128; k++) accr += rs[base + k] * __ldg(&W1[(270 + k) * 128 + j]);
            ((__half*)g_rp)[(size_t)r * 128 + j] = __float2half(accc + accr);
        }
    }
}

// ---------------------------------------------------------------------------
// GEMM: AB[N,256] = h_e[N,144] @ Wcat[144,256], single-product fp16 mma.sync,
// fp32 accum. Block 128x128, 8 warps (2x4), warp tile 64x32, BK=16, cp.async
// double-buffered; last k-tile (cols 128..143) synthesized from DDE state.
// ---------------------------------------------------------------------------
#define APITCH 24   // smem row pitch in fp16 (48B -> conflict-free ldmatrix)
#define R_EL   (128 * APITCH)   // elements per region (3072)

__device__ __forceinline__ void ldsm4(unsigned* r, unsigned a) {
    asm volatile("ldmatrix.sync.aligned.m8n8.x4.shared.b16 {%0,%1,%2,%3}, [%4];"
                 : "=r"(r[0]), "=r"(r[1]), "=r"(r[2]), "=r"(r[3]) : "r"(a));
}
__device__ __forceinline__ void mma_f16(float* d, const unsigned* a, unsigned b0, unsigned b1) {
    asm volatile("mma.sync.aligned.m16n8k16.row.col.f32.f16.f16.f32 "
                 "{%0,%1,%2,%3}, {%4,%5,%6,%7}, {%8,%9}, {%0,%1,%2,%3};"
                 : "+f"(d[0]), "+f"(d[1]), "+f"(d[2]), "+f"(d[3])
                 : "r"(a[0]), "r"(a[1]), "r"(a[2]), "r"(a[3]), "r"(b0), "r"(b1));
}
__device__ __forceinline__ void cp16(unsigned dst, const void* src) {
    asm volatile("cp.async.ca.shared.global [%0], [%1], 16;" :: "r"(dst), "l"(src));
}

__global__ __launch_bounds__(256) void k_gemm(const float* __restrict__ topic, int Nn) {
    // smem regions (fp16 elements): Abuf0 [0,R) Abuf1 [R,2R) Bbuf0 [2R,3R) Bbuf1 [3R,4R)
    __shared__ __align__(16) __half sm[4 * R_EL];     // 24 KB
    unsigned smb = (unsigned)__cvta_generic_to_shared(sm);
    int tid = threadIdx.x;
    int m0 = blockIdx.x * 128, n0 = blockIdx.y * 128;
    int wid = tid >> 5, lane = tid & 31;
    int wm = (wid >> 2) * 64, wn = (wid & 3) * 32;

    // staging: slot 0 = A, slot 1 = B; per tile each thread copies one 16B unit.
    int row = tid >> 1, half = tid & 1;                // 128 rows x 2 halves
    const __half* gbase[2];
    unsigned dstoff[2];                                // bytes, excluding buf
    {
        int gr = m0 + row; if (gr >= Nn) gr = Nn - 1;
        gbase[0] = g_hef + (size_t)gr * HE_W + half * 8;
        gbase[1] = g_wf + (size_t)(n0 + row) * HE_W + half * 8;
        dstoff[0] = (unsigned)(row * APITCH + half * 8) * 2;
        dstoff[1] = (unsigned)(2 * R_EL + row * APITCH + half * 8) * 2;
    }
    const unsigned bufstride = R_EL * 2;               // bytes between buf0/buf1

    float acc[4][4][4];
#pragma unroll
    for (int i = 0; i < 4; i++)
#pragma unroll
        for (int j = 0; j < 4; j++)
#pragma unroll
            for (int k = 0; k < 4; k++) acc[i][j][k] = 0.f;

    int ldrow = lane & 15, ldk = (lane >> 4) * 8;

    // ---- prologue: stage tile 0 into buf 0 ----
    cp16(smb + dstoff[0], gbase[0]);
    cp16(smb + dstoff[1], gbase[1]);
    asm volatile("cp.async.commit_group;");

    for (int it = 0; it <= 8; ++it) {
        int buf = it & 1;
        asm volatile("cp.async.wait_group 0;");
        __syncthreads();

        if (it < 8) {
            unsigned bofs = (buf ^ 1) * bufstride;
            if (it + 1 < 8) {
                cp16(smb + bofs + dstoff[0], gbase[0] + (it + 1) * 16);
                cp16(smb + bofs + dstoff[1], gbase[1] + (it + 1) * 16);
            } else {
                // tile 8: B via cp.async (Wcat cols 128..143), A synthesized
                cp16(smb + bofs + dstoff[1], gbase[1] + 8 * 16);
                int i = m0 + row; if (i >= Nn) i = Nn - 1;
                float v[8];
                if (half == 0) {  // cols 128..135: topic, fwd rounds 1..3
                    float2 tp = __ldg(((const float2*)topic) + i);
                    float4 f0 = g_f0[i];
                    float2 f1 = g_f1[i], f2 = g_f2[i];
                    float ict = 1.0f / fmaxf(f0.z, 1.0f);
                    v[0] = tp.x;       v[1] = tp.y;
                    v[2] = f0.x * ict; v[3] = f0.y * ict;
                    v[4] = f1.x * ict; v[5] = f1.y * ict;
                    v[6] = f2.x * ict; v[7] = f2.y * ict;
                } else {          // cols 136..143: rev rounds 1..3, pad
                    float4 r0 = g_r0[i];
                    float2 r1 = g_r1[i], r2 = g_r2[i];
                    float ich = 1.0f / fmaxf(r0.z, 1.0f);
                    v[0] = r0.x * ich; v[1] = r0.y * ich;
                    v[2] = r1.x * ich; v[3] = r1.y * ich;
                    v[4] = r2.x * ich; v[5] = r2.y * ich;
                    v[6] = 0.f;        v[7] = 0.f;
                }
                *(uint4*)((char*)sm + bofs + dstoff[0]) =
                    make_uint4(packh2(v[0], v[1]), packh2(v[2], v[3]),
                               packh2(v[4], v[5]), packh2(v[6], v[7]));
            }
            asm volatile("cp.async.commit_group;");
        }

        // ---- fragments from buf ----
        unsigned aoff = buf * bufstride;
        unsigned Af[4][4], Bf[2][4];
#pragma unroll
        for (int mf = 0; mf < 4; mf++) {
            unsigned r = (wm + mf * 16 + ldrow) * APITCH + ldk;
            ldsm4(Af[mf], smb + aoff + r * 2);
        }
#pragma unroll
        for (int nh = 0; nh < 2; nh++) {
            unsigned r = (wn + nh * 16 + ldrow) * APITCH + ldk;
            ldsm4(Bf[nh], smb + 2 * R_EL * 2 + aoff + r * 2);
        }
#pragma unroll
        for (int mf = 0; mf < 4; mf++)
#pragma unroll
            for (int nf = 0; nf < 4; nf++) {
                int nh = nf >> 1, sel = nf & 1;
                mma_f16(acc[mf][nf], Af[mf], Bf[nh][sel], Bf[nh][sel + 2]);
            }
        if (it < 8) __syncthreads();
    }

    // ---- epilogue: fp32 acc -> fp16 AB ----
    int g = lane >> 2, tg = lane & 3;
    unsigned* outw = (unsigned*)g_ab;
#pragma unroll
    for (int mf = 0; mf < 4; mf++)
#pragma unroll
        for (int nf = 0; nf < 4; nf++) {
            int col = n0 + wn + nf * 8 + 2 * tg;
            int r0 = m0 + wm + mf * 16 + g;
            if (r0 < Nn)
                outw[(size_t)r0 * 128 + (col >> 1)] = packh2(acc[mf][nf][0], acc[mf][nf][1]);
            int r1 = r0 + 8;
            if (r1 < Nn)
                outw[(size_t)r1 * 128 + (col >> 1)] = packh2(acc[mf][nf][2], acc[mf][nf][3]);
        }
}

// -------- edge stage: 16 lanes per edge, uint4 (LDG.128) gathers --------------
__global__ __launch_bounds__(256) void k_edge(float* __restrict__ out,
                                              const float4* __restrict__ w2,
                                              const float* __restrict__ b2, int E) {
    int gt = blockIdx.x * 256 + threadIdx.x;
    int e = gt >> 4, sub = gt & 15;
    bool valid = (e < E);
    if (e >= E) e = E - 1;
    int h = g_hh[e], t = g_tt[e], r = g_rr[e];
    uint4 ua = __ldg(&g_ab[(size_t)h * 32 + sub]);        // cols 8s..8s+7 of A
    uint4 ub = __ldg(&g_ab[(size_t)t * 32 + 16 + sub]);   // cols 8s..8s+7 of B
    uint4 ur = __ldg(&g_rp[(size_t)r * 16 + sub]);        // R' (c, b1 folded in)
    float4 w0 = __ldg(&w2[2 * sub]);
    float4 w1 = __ldg(&w2[2 * sub + 1]);
    float2 a0 = h22f(ua.x), a1 = h22f(ua.y), a2 = h22f(ua.z), a3 = h22f(ua.w);
    float2 b0 = h22f(ub.x), b1 = h22f(ub.y), b2v = h22f(ub.z), b3 = h22f(ub.w);
    float2 r0 = h22f(ur.x), r1 = h22f(ur.y), r2 = h22f(ur.z), r3 = h22f(ur.w);
    float s = fmaxf(a0.x + b0.x + r0.x, 0.f) * w0.x
            + fmaxf(a0.y + b0.y + r0.y, 0.f) * w0.y
            + fmaxf(a1.x + b1.x + r1.x, 0.f) * w0.z
            + fmaxf(a1.y + b1.y + r1.y, 0.f) * w0.w
            + fmaxf(a2.x + b2v.x + r2.x, 0.f) * w1.x
            + fmaxf(a2.y + b2v.y + r2.y, 0.f) * w1.y
            + fmaxf(a3.x + b3.x + r3.x, 0.f) * w1.z
            + fmaxf(a3.y + b3.y + r3.y, 0.f) * w1.w;
    s += __shfl_xor_sync(0xffffffff, s, 8);
    s += __shfl_xor_sync(0xffffffff, s, 4);
    s += __shfl_xor_sync(0xffffffff, s, 2);
    s += __shfl_xor_sync(0xffffffff, s, 1);
    if (valid && sub == 0) out[e] = s + __ldg(b2);
}

// ---------------------------------------------------------------------------
// Streams/events created in a static initializer (before harness checkpoints).
struct HxRes {
    cudaStream_t s1, s2;
    cudaEvent_t e0, e1, e2;
    HxRes() {
        cudaStreamCreateWithFlags(&s1, cudaStreamNonBlocking);
        cudaStreamCreateWithFlags(&s2, cudaStreamNonBlocking);
        cudaEventCreateWithFlags(&e0, cudaEventDisableTiming);
        cudaEventCreateWithFlags(&e1, cudaEventDisableTiming);
        cudaEventCreateWithFlags(&e2, cudaEventDisableTiming);
    }
};
static HxRes hx;

extern "C" void kernel_launch(void* const* d_in, const int* in_sizes, int n_in,
                              void* d_out, int out_size) {
    int off = (n_in >= 13) ? 0 : -1;   // robust to scalar input being dropped
    const void*  ph    = d_in[0];
    const void*  pr    = d_in[1];
    const void*  pt    = d_in[2];
    const float* q     = (const float*)d_in[3];
    const float* ent   = (const float*)d_in[4];
    const float* rel   = (const float*)d_in[6 + off];
    const float* topic = (const float*)d_in[7 + off];
    const float* nont  = (const float*)d_in[8 + off];
    const float* W1    = (const float*)d_in[9 + off];
    const float* b1    = (const float*)d_in[10 + off];
    const float* W2    = (const float*)d_in[11 + off];
    const float* b2    = (const float*)d_in[12 + off];

    int E     = in_sizes[0];
    int Ntext = in_sizes[4] / 128;
    int NREL  = in_sizes[6 + off] / 128;
    int Nn    = in_sizes[7 + off] / 2;
    if (E > E_MAX) E = E_MAX;
    if (Nn > N_MAX) Nn = N_MAX;
    if (NREL > 512) NREL = 512;

    int gE = (E + 255) / 256;
    int nrelb = (NREL + 1) / 2;

    // fork: fill on s1, prep on s2, DDE chain on the main stream (R5 skeleton)
    cudaEventRecord(hx.e0, 0);
    cudaStreamWaitEvent(hx.s1, hx.e0, 0);
    cudaStreamWaitEvent(hx.s2, hx.e0, 0);

    k_fill<<<(Nn * 32 + 255) / 256, 256, 0, hx.s1>>>(ent, nont, Nn, Ntext);
    cudaEventRecord(hx.e1, hx.s1);

    k_prep<<<144 + nrelb, 256, 0, hx.s2>>>(W1, rel, q, b1, NREL);
    cudaEventRecord(hx.e2, hx.s2);

    k_convert<<<gE, 256>>>(ph, pr, pt, topic, E);   // ids + DDE round 0 + counts
    k_scat<<<gE, 256>>>(1, E);                      // DDE round 1 -> 2
    k_scat<<<gE, 256>>>(2, E);                      // DDE round 2 -> 3

    // join: gemm needs fill (A), prep (Wcat) and the DDE chain (this stream)
    cudaStreamWaitEvent(0, hx.e1, 0);
    cudaStreamWaitEvent(0, hx.e2, 0);
    dim3 ggrid((Nn + 127) / 128, 2);
    k_gemm<<<ggrid, 256>>>(topic, Nn);

    k_edge<<<(E * 16 + 255) / 256, 256>>>((float*)d_out, (const float4*)W2, b2, E);
}

// round 9
// speedup vs baseline: 2.0016x; 1.0381x over previous
#include <cuda_runtime.h>
#include <cuda_bf16.h>
#include <cuda_fp16.h>

// ---------------------------------------------------------------------------
// Retriever: out[e] = relu([q | h_e[h] | r_emb[r] | h_e[t]] @ W1 + b1) @ W2 + b2
//   R'     = rel_embs @ W1[270:398] + (q @ W1[0:128] + b1)    (500 x 128, fp16)
//   AB     = h_e @ [W1[128:270] | W1[398:540]]                (N x 256, fp16)
//            single-product fp16 mma.sync GEMM (fp32 accum); DDE columns
//            synthesized into SMEM inside the GEMM.
//   out[e] = W2 . relu(AB[h,0:128] + AB[t,128:256] + R'[r]) + b2
// NOTES: harness PTX targets plain sm_100 -> tcgen05 unavailable; mma.sync only.
//        R7 lesson: do NOT overlap the GEMM with the DDE atomic chain (L2
//        contention regressed 207->311); serial ordering kept.
//        R9: edge/convert/scat process 2 edges per thread (MLP doubling) --
//        these kernels are L2-latency bound (issue ~9%, occ ~78%).
// ---------------------------------------------------------------------------

#define E_MAX 500000
#define N_MAX 100000
#define HE_W  144      // row pitch in fp16 for h_e / Wcat (142 used, 2 zero)

__device__ int    g_hh[E_MAX];
__device__ int    g_tt[E_MAX];
__device__ int    g_rr[E_MAX];
__device__ float4 g_f0[N_MAX];                         // fwd r1 sums + cnt_t in .z
__device__ float4 g_r0[N_MAX];                         // rev r1 sums + cnt_h in .z
__device__ float2 g_f1[N_MAX], g_f2[N_MAX];            // fwd rounds 2,3 sums
__device__ float2 g_r1[N_MAX], g_r2[N_MAX];            // rev rounds 2,3 sums
__device__ __half g_hef[(size_t)N_MAX * HE_W];         // h_e fp16 (cols 0..127)
__device__ __half g_wf[256 * HE_W];                    // Wcat fp16, [n][k]
__device__ uint4  g_ab[(size_t)N_MAX * 32];            // AB  [N,256] fp16
__device__ uint4  g_rp[512 * 16];                      // R' [NREL,128] fp16

__device__ __forceinline__ unsigned packh2(float x, float y) {
    __half2 t = __floats2half2_rn(x, y);
    return *(unsigned*)&t;
}
__device__ __forceinline__ float2 h22f(unsigned u) {
    return __half22float2(*(__half2*)&u);
}
__device__ __forceinline__ void red2(float2* p, float x, float y) {
    asm volatile("red.global.add.v2.f32 [%0], {%1, %2};"
                 :: "l"(p), "f"(x), "f"(y) : "memory");
}
__device__ __forceinline__ void red4(float4* p, float x, float y, float z, float w) {
    asm volatile("red.global.add.v4.f32 [%0], {%1, %2, %3, %4};"
                 :: "l"(p), "f"(x), "f"(y), "f"(z), "f"(w) : "memory");
}

// ---------------- build h_e fp16 cols 0..127 + zero DDE state ----------------
__global__ void k_fill(const float* __restrict__ ent, const float* __restrict__ nont,
                       int Nn, int Ntext) {
    int i = blockIdx.x * 256 + threadIdx.x;
    if (i >= Nn * 32) return;
    int node = i >> 5, c4 = i & 31;
    const float* src = (node < Ntext) ? (ent + (size_t)node * 128 + c4 * 4)
                                      : (nont + c4 * 4);
    float4 v = *(const float4*)src;
    *(uint2*)(g_hef + (size_t)node * HE_W + c4 * 4) =
        make_uint2(packh2(v.x, v.y), packh2(v.z, v.w));
    if (c4 == 0) {   // piggyback: zero DDE accumulators
        g_f0[node] = make_float4(0.f, 0.f, 0.f, 0.f);
        g_r0[node] = make_float4(0.f, 0.f, 0.f, 0.f);
        g_f1[node] = make_float2(0.f, 0.f);
        g_f2[node] = make_float2(0.f, 0.f);
        g_r1[node] = make_float2(0.f, 0.f);
        g_r2[node] = make_float2(0.f, 0.f);
    }
}

// ------- ids -> int32 (+dtype detect) + DDE round 0; 2 edges per thread -------
__global__ void k_convert(const void* ph, const void* pr, const void* pt,
                          const float* __restrict__ topic, int E) {
    __shared__ int s64;
    if (threadIdx.x == 0) {
        // int64 vs int32: int64 view of int32 r-id buffer is >= 2^32 a.s.
        const long long* p = (const long long*)ph;
        const long long* qq = (const long long*)pr;
        int ok = 1;
        for (int i = 0; i < 8; i++) {
            long long v = p[i];  if (v < 0 || v >= 1000000) ok = 0;
            long long w = qq[i]; if (w < 0 || w >= 1000000) ok = 0;
        }
        s64 = ok;
    }
    __syncthreads();
    int base = (blockIdx.x * 256 + threadIdx.x) * 2;
    if (base >= E) return;
    int n2 = (base + 1 < E) ? 2 : 1;
    int h[2], r[2], t[2];
#pragma unroll
    for (int j = 0; j < 2; j++) {
        int e = base + ((j < n2) ? j : 0);
        if (s64) {
            h[j] = (int)((const long long*)ph)[e];
            r[j] = (int)((const long long*)pr)[e];
            t[j] = (int)((const long long*)pt)[e];
        } else {
            h[j] = ((const int*)ph)[e];
            r[j] = ((const int*)pr)[e];
            t[j] = ((const int*)pt)[e];
        }
    }
    const float2* tp2 = (const float2*)topic;
    float2 th0 = __ldg(tp2 + h[0]);
    float2 tt0 = __ldg(tp2 + t[0]);
    float2 th1 = __ldg(tp2 + h[1]);
    float2 tt1 = __ldg(tp2 + t[1]);
    g_hh[base] = h[0]; g_rr[base] = r[0]; g_tt[base] = t[0];
    red4(&g_f0[t[0]], th0.x, th0.y, 1.0f, 0.f);
    red4(&g_r0[h[0]], tt0.x, tt0.y, 1.0f, 0.f);
    if (n2 == 2) {
        g_hh[base + 1] = h[1]; g_rr[base + 1] = r[1]; g_tt[base + 1] = t[1];
        red4(&g_f0[t[1]], th1.x, th1.y, 1.0f, 0.f);
        red4(&g_r0[h[1]], tt1.x, tt1.y, 1.0f, 0.f);
    }
}

// ------- DDE scatter round rd (1 or 2); 2 edges per thread --------------------
__global__ void k_scat(int rd, int E) {
    int base = (blockIdx.x * 256 + threadIdx.x) * 2;
    if (base >= E) return;
    int n2 = (base + 1 < E) ? 2 : 1;
    int e1 = (n2 == 2) ? base + 1 : base;
    int h0 = g_hh[base], t0 = g_tt[base];
    int h1 = g_hh[e1],   t1 = g_tt[e1];
    if (rd == 1) {
        float4 f0h0 = __ldg(&g_f0[h0]);
        float4 r0t0 = __ldg(&g_r0[t0]);
        float4 f0h1 = __ldg(&g_f0[h1]);
        float4 r0t1 = __ldg(&g_r0[t1]);
        float ia = 1.0f / fmaxf(f0h0.z, 1.0f);
        float ib = 1.0f / fmaxf(r0t0.z, 1.0f);
        float ic = 1.0f / fmaxf(f0h1.z, 1.0f);
        float id = 1.0f / fmaxf(r0t1.z, 1.0f);
        red2(&g_f1[t0], f0h0.x * ia, f0h0.y * ia);
        red2(&g_r1[h0], r0t0.x * ib, r0t0.y * ib);
        if (n2 == 2) {
            red2(&g_f1[t1], f0h1.x * ic, f0h1.y * ic);
            red2(&g_r1[h1], r0t1.x * id, r0t1.y * id);
        }
    } else {
        const float* cb = (const float*)g_f0;
        const float* ch = (const float*)g_r0;
        float ca0 = __ldg(cb + 4 * (size_t)h0 + 2);
        float cb0 = __ldg(ch + 4 * (size_t)t0 + 2);
        float ca1 = __ldg(cb + 4 * (size_t)h1 + 2);
        float cb1 = __ldg(ch + 4 * (size_t)t1 + 2);
        float2 f1h0 = __ldg(&g_f1[h0]);
        float2 r1t0 = __ldg(&g_r1[t0]);
        float2 f1h1 = __ldg(&g_f1[h1]);
        float2 r1t1 = __ldg(&g_r1[t1]);
        float ia = 1.0f / fmaxf(ca0, 1.0f);
        float ib = 1.0f / fmaxf(cb0, 1.0f);
        float ic = 1.0f / fmaxf(ca1, 1.0f);
        float id = 1.0f / fmaxf(cb1, 1.0f);
        red2(&g_f2[t0], f1h0.x * ia, f1h0.y * ia);
        red2(&g_r2[h0], r1t0.x * ib, r1t0.y * ib);
        if (n2 == 2) {
            red2(&g_f2[t1], f1h1.x * ic, f1h1.y * ic);
            red2(&g_r2[h1], r1t1.x * id, r1t1.y * id);
        }
    }
}

// ------- prep: Wcat fp16 [n][k] | R' = rel@W1_r + (q@W1_q + b1), fp16 ----------
__global__ void k_prep(const float* __restrict__ W1, const float* __restrict__ rel,
                       const float* __restrict__ q, const float* __restrict__ b1,
                       int NREL) {
    int bid = blockIdx.x;
    int tid = threadIdx.x;
    if (bid < 144) {                       // Wcat: 256 elements of the [n][k] array
        int idx = bid * 256 + tid;
        int n = idx / 144, k = idx % 144;
        float v = 0.f;
        if (k < 142) v = (n < 128) ? W1[(128 + k) * 128 + n]
                                   : W1[(398 + k) * 128 + (n - 128)];
        g_wf[idx] = __float2half(v);
    } else {                               // two relations per block
        __shared__ float rs[256];
        __shared__ float qs[128];
        int r = (bid - 144) * 2 + (tid >> 7);
        int j = tid & 127;
        int base = tid & ~127;
        if (tid < 128) qs[tid] = q[tid];
        rs[tid] = (r < NREL) ? rel[(size_t)r * 128 + j] : 0.f;
        __syncthreads();
        if (r < NREL) {
            float accc = b1[j];
#pragma unroll 8
            for (int k = 0; k < 128; k++) accc += qs[k] * __ldg(&W1[k * 128 + j]);
            float accr = 0.f;
#pragma unroll 8
            for (int k = 0; k < 128; k++) accr += rs[base + k] * __ldg(&W1[(270 + k) * 128 + j]);
            ((__half*)g_rp)[(size_t)r * 128 + j] = __float2half(accc + accr);
        }
    }
}

// ---------------------------------------------------------------------------
// GEMM: AB[N,256] = h_e[N,144] @ Wcat[144,256], single-product fp16 mma.sync,
// fp32 accum. Block 128x128, 8 warps (2x4), warp tile 64x32, BK=16, cp.async
// double-buffered; last k-tile (cols 128..143) synthesized from DDE state.
// ---------------------------------------------------------------------------
#define APITCH 24   // smem row pitch in fp16 (48B -> conflict-free ldmatrix)
#define R_EL   (128 * APITCH)   // elements per region (3072)

__device__ __forceinline__ void ldsm4(unsigned* r, unsigned a) {
    asm volatile("ldmatrix.sync.aligned.m8n8.x4.shared.b16 {%0,%1,%2,%3}, [%4];"
                 : "=r"(r[0]), "=r"(r[1]), "=r"(r[2]), "=r"(r[3]) : "r"(a));
}
__device__ __forceinline__ void mma_f16(float* d, const unsigned* a, unsigned b0, unsigned b1) {
    asm volatile("mma.sync.aligned.m16n8k16.row.col.f32.f16.f16.f32 "
                 "{%0,%1,%2,%3}, {%4,%5,%6,%7}, {%8,%9}, {%0,%1,%2,%3};"
                 : "+f"(d[0]), "+f"(d[1]), "+f"(d[2]), "+f"(d[3])
                 : "r"(a[0]), "r"(a[1]), "r"(a[2]), "r"(a[3]), "r"(b0), "r"(b1));
}
__device__ __forceinline__ void cp16(unsigned dst, const void* src) {
    asm volatile("cp.async.ca.shared.global [%0], [%1], 16;" :: "r"(dst), "l"(src));
}

__global__ __launch_bounds__(256) void k_gemm(const float* __restrict__ topic, int Nn) {
    // smem regions (fp16 elements): Abuf0 [0,R) Abuf1 [R,2R) Bbuf0 [2R,3R) Bbuf1 [3R,4R)
    __shared__ __align__(16) __half sm[4 * R_EL];     // 24 KB
    unsigned smb = (unsigned)__cvta_generic_to_shared(sm);
    int tid = threadIdx.x;
    int m0 = blockIdx.x * 128, n0 = blockIdx.y * 128;
    int wid = tid >> 5, lane = tid & 31;
    int wm = (wid >> 2) * 64, wn = (wid & 3) * 32;

    // staging: slot 0 = A, slot 1 = B; per tile each thread copies one 16B unit.
    int row = tid >> 1, half = tid & 1;                // 128 rows x 2 halves
    const __half* gbase[2];
    unsigned dstoff[2];                                // bytes, excluding buf
    {
        int gr = m0 + row; if (gr >= Nn) gr = Nn - 1;
        gbase[0] = g_hef + (size_t)gr * HE_W + half * 8;
        gbase[1] = g_wf + (size_t)(n0 + row) * HE_W + half * 8;
        dstoff[0] = (unsigned)(row * APITCH + half * 8) * 2;
        dstoff[1] = (unsigned)(2 * R_EL + row * APITCH + half * 8) * 2;
    }
    const unsigned bufstride = R_EL * 2;               // bytes between buf0/buf1

    float acc[4][4][4];
#pragma unroll
    for (int i = 0; i < 4; i++)
#pragma unroll
        for (int j = 0; j < 4; j++)
#pragma unroll
            for (int k = 0; k < 4; k++) acc[i][j][k] = 0.f;

    int ldrow = lane & 15, ldk = (lane >> 4) * 8;

    // ---- prologue: stage tile 0 into buf 0 ----
    cp16(smb + dstoff[0], gbase[0]);
    cp16(smb + dstoff[1], gbase[1]);
    asm volatile("cp.async.commit_group;");

    for (int it = 0; it <= 8; ++it) {
        int buf = it & 1;
        asm volatile("cp.async.wait_group 0;");
        __syncthreads();

        if (it < 8) {
            unsigned bofs = (buf ^ 1) * bufstride;
            if (it + 1 < 8) {
                cp16(smb + bofs + dstoff[0], gbase[0] + (it + 1) * 16);
                cp16(smb + bofs + dstoff[1], gbase[1] + (it + 1) * 16);
            } else {
                // tile 8: B via cp.async (Wcat cols 128..143), A synthesized
                cp16(smb + bofs + dstoff[1], gbase[1] + 8 * 16);
                int i = m0 + row; if (i >= Nn) i = Nn - 1;
                float v[8];
                if (half == 0) {  // cols 128..135: topic, fwd rounds 1..3
                    float2 tp = __ldg(((const float2*)topic) + i);
                    float4 f0 = g_f0[i];
                    float2 f1 = g_f1[i], f2 = g_f2[i];
                    float ict = 1.0f / fmaxf(f0.z, 1.0f);
                    v[0] = tp.x;       v[1] = tp.y;
                    v[2] = f0.x * ict; v[3] = f0.y * ict;
                    v[4] = f1.x * ict; v[5] = f1.y * ict;
                    v[6] = f2.x * ict; v[7] = f2.y * ict;
                } else {          // cols 136..143: rev rounds 1..3, pad
                    float4 r0 = g_r0[i];
                    float2 r1 = g_r1[i], r2 = g_r2[i];
                    float ich = 1.0f / fmaxf(r0.z, 1.0f);
                    v[0] = r0.x * ich; v[1] = r0.y * ich;
                    v[2] = r1.x * ich; v[3] = r1.y * ich;
                    v[4] = r2.x * ich; v[5] = r2.y * ich;
                    v[6] = 0.f;        v[7] = 0.f;
                }
                *(uint4*)((char*)sm + bofs + dstoff[0]) =
                    make_uint4(packh2(v[0], v[1]), packh2(v[2], v[3]),
                               packh2(v[4], v[5]), packh2(v[6], v[7]));
            }
            asm volatile("cp.async.commit_group;");
        }

        // ---- fragments from buf ----
        unsigned aoff = buf * bufstride;
        unsigned Af[4][4], Bf[2][4];
#pragma unroll
        for (int mf = 0; mf < 4; mf++) {
            unsigned r = (wm + mf * 16 + ldrow) * APITCH + ldk;
            ldsm4(Af[mf], smb + aoff + r * 2);
        }
#pragma unroll
        for (int nh = 0; nh < 2; nh++) {
            unsigned r = (wn + nh * 16 + ldrow) * APITCH + ldk;
            ldsm4(Bf[nh], smb + 2 * R_EL * 2 + aoff + r * 2);
        }
#pragma unroll
        for (int mf = 0; mf < 4; mf++)
#pragma unroll
            for (int nf = 0; nf < 4; nf++) {
                int nh = nf >> 1, sel = nf & 1;
                mma_f16(acc[mf][nf], Af[mf], Bf[nh][sel], Bf[nh][sel + 2]);
            }
        if (it < 8) __syncthreads();
    }

    // ---- epilogue: fp32 acc -> fp16 AB ----
    int g = lane >> 2, tg = lane & 3;
    unsigned* outw = (unsigned*)g_ab;
#pragma unroll
    for (int mf = 0; mf < 4; mf++)
#pragma unroll
        for (int nf = 0; nf < 4; nf++) {
            int col = n0 + wn + nf * 8 + 2 * tg;
            int r0 = m0 + wm + mf * 16 + g;
            if (r0 < Nn)
                outw[(size_t)r0 * 128 + (col >> 1)] = packh2(acc[mf][nf][0], acc[mf][nf][1]);
            int r1 = r0 + 8;
            if (r1 < Nn)
                outw[(size_t)r1 * 128 + (col >> 1)] = packh2(acc[mf][nf][2], acc[mf][nf][3]);
        }
}

// -------- edge stage: 2 edges per 16-lane group, 6 batched uint4 gathers ------
__global__ __launch_bounds__(256) void k_edge(float* __restrict__ out,
                                              const float4* __restrict__ w2,
                                              const float* __restrict__ b2, int E) {
    int gt = blockIdx.x * 256 + threadIdx.x;
    int pair = gt >> 4, sub = gt & 15;
    int e0 = pair * 2, e1 = pair * 2 + 1;
    bool v0 = (e0 < E), v1 = (e1 < E);
    if (!v0) e0 = E - 1;
    if (!v1) e1 = E - 1;
    int h0 = g_hh[e0], t0 = g_tt[e0], r0i = g_rr[e0];
    int h1 = g_hh[e1], t1 = g_tt[e1], r1i = g_rr[e1];
    // issue all 6 gathers before any use (MLP=6)
    uint4 ua0 = __ldg(&g_ab[(size_t)h0 * 32 + sub]);
    uint4 ub0 = __ldg(&g_ab[(size_t)t0 * 32 + 16 + sub]);
    uint4 ur0 = __ldg(&g_rp[(size_t)r0i * 16 + sub]);
    uint4 ua1 = __ldg(&g_ab[(size_t)h1 * 32 + sub]);
    uint4 ub1 = __ldg(&g_ab[(size_t)t1 * 32 + 16 + sub]);
    uint4 ur1 = __ldg(&g_rp[(size_t)r1i * 16 + sub]);
    float4 w0 = __ldg(&w2[2 * sub]);
    float4 w1 = __ldg(&w2[2 * sub + 1]);

    float s0, s1;
    {
        float2 a0 = h22f(ua0.x), a1 = h22f(ua0.y), a2 = h22f(ua0.z), a3 = h22f(ua0.w);
        float2 b0v = h22f(ub0.x), b1v = h22f(ub0.y), b2v = h22f(ub0.z), b3v = h22f(ub0.w);
        float2 c0 = h22f(ur0.x), c1 = h22f(ur0.y), c2 = h22f(ur0.z), c3 = h22f(ur0.w);
        s0 = fmaxf(a0.x + b0v.x + c0.x, 0.f) * w0.x
           + fmaxf(a0.y + b0v.y + c0.y, 0.f) * w0.y
           + fmaxf(a1.x + b1v.x + c1.x, 0.f) * w0.z
           + fmaxf(a1.y + b1v.y + c1.y, 0.f) * w0.w
           + fmaxf(a2.x + b2v.x + c2.x, 0.f) * w1.x
           + fmaxf(a2.y + b2v.y + c2.y, 0.f) * w1.y
           + fmaxf(a3.x + b3v.x + c3.x, 0.f) * w1.z
           + fmaxf(a3.y + b3v.y + c3.y, 0.f) * w1.w;
    }
    {
        float2 a0 = h22f(ua1.x), a1 = h22f(ua1.y), a2 = h22f(ua1.z), a3 = h22f(ua1.w);
        float2 b0v = h22f(ub1.x), b1v = h22f(ub1.y), b2v = h22f(ub1.z), b3v = h22f(ub1.w);
        float2 c0 = h22f(ur1.x), c1 = h22f(ur1.y), c2 = h22f(ur1.z), c3 = h22f(ur1.w);
        s1 = fmaxf(a0.x + b0v.x + c0.x, 0.f) * w0.x
           + fmaxf(a0.y + b0v.y + c0.y, 0.f) * w0.y
           + fmaxf(a1.x + b1v.x + c1.x, 0.f) * w0.z
           + fmaxf(a1.y + b1v.y + c1.y, 0.f) * w0.w
           + fmaxf(a2.x + b2v.x + c2.x, 0.f) * w1.x
           + fmaxf(a2.y + b2v.y + c2.y, 0.f) * w1.y
           + fmaxf(a3.x + b3v.x + c3.x, 0.f) * w1.z
           + fmaxf(a3.y + b3v.y + c3.y, 0.f) * w1.w;
    }
    s0 += __shfl_xor_sync(0xffffffff, s0, 8);
    s1 += __shfl_xor_sync(0xffffffff, s1, 8);
    s0 += __shfl_xor_sync(0xffffffff, s0, 4);
    s1 += __shfl_xor_sync(0xffffffff, s1, 4);
    s0 += __shfl_xor_sync(0xffffffff, s0, 2);
    s1 += __shfl_xor_sync(0xffffffff, s1, 2);
    s0 += __shfl_xor_sync(0xffffffff, s0, 1);
    s1 += __shfl_xor_sync(0xffffffff, s1, 1);
    if (sub == 0) {
        float bb = __ldg(b2);
        if (v0) out[e0] = s0 + bb;
        if (v1) out[e1] = s1 + bb;
    }
}

// ---------------------------------------------------------------------------
// Streams/events created in a static initializer (before harness checkpoints).
struct HxRes {
    cudaStream_t s1, s2;
    cudaEvent_t e0, e1, e2;
    HxRes() {
        cudaStreamCreateWithFlags(&s1, cudaStreamNonBlocking);
        cudaStreamCreateWithFlags(&s2, cudaStreamNonBlocking);
        cudaEventCreateWithFlags(&e0, cudaEventDisableTiming);
        cudaEventCreateWithFlags(&e1, cudaEventDisableTiming);
        cudaEventCreateWithFlags(&e2, cudaEventDisableTiming);
    }
};
static HxRes hx;

extern "C" void kernel_launch(void* const* d_in, const int* in_sizes, int n_in,
                              void* d_out, int out_size) {
    int off = (n_in >= 13) ? 0 : -1;   // robust to scalar input being dropped
    const void*  ph    = d_in[0];
    const void*  pr    = d_in[1];
    const void*  pt    = d_in[2];
    const float* q     = (const float*)d_in[3];
    const float* ent   = (const float*)d_in[4];
    const float* rel   = (const float*)d_in[6 + off];
    const float* topic = (const float*)d_in[7 + off];
    const float* nont  = (const float*)d_in[8 + off];
    const float* W1    = (const float*)d_in[9 + off];
    const float* b1    = (const float*)d_in[10 + off];
    const float* W2    = (const float*)d_in[11 + off];
    const float* b2    = (const float*)d_in[12 + off];

    int E     = in_sizes[0];
    int Ntext = in_sizes[4] / 128;
    int NREL  = in_sizes[6 + off] / 128;
    int Nn    = in_sizes[7 + off] / 2;
    if (E > E_MAX) E = E_MAX;
    if (Nn > N_MAX) Nn = N_MAX;
    if (NREL > 512) NREL = 512;

    int gE2 = ((E + 1) / 2 + 255) / 256;     // 2 edges per thread
    int nrelb = (NREL + 1) / 2;

    // fork: fill on s1, prep on s2, DDE chain on the main stream
    cudaEventRecord(hx.e0, 0);
    cudaStreamWaitEvent(hx.s1, hx.e0, 0);
    cudaStreamWaitEvent(hx.s2, hx.e0, 0);

    k_fill<<<(Nn * 32 + 255) / 256, 256, 0, hx.s1>>>(ent, nont, Nn, Ntext);
    cudaEventRecord(hx.e1, hx.s1);

    k_prep<<<144 + nrelb, 256, 0, hx.s2>>>(W1, rel, q, b1, NREL);
    cudaEventRecord(hx.e2, hx.s2);

    k_convert<<<gE2, 256>>>(ph, pr, pt, topic, E);   // ids + DDE round 0 + counts
    k_scat<<<gE2, 256>>>(1, E);                      // DDE round 1 -> 2
    k_scat<<<gE2, 256>>>(2, E);                      // DDE round 2 -> 3

    // join: gemm needs fill (A), prep (Wcat) and the DDE chain (this stream)
    cudaStreamWaitEvent(0, hx.e1, 0);
    cudaStreamWaitEvent(0, hx.e2, 0);
    dim3 ggrid((Nn + 127) / 128, 2);
    k_gemm<<<ggrid, 256>>>(topic, Nn);

    // 2 edges per 16-lane group -> E*8 threads
    k_edge<<<(E * 8 + 255) / 256, 256>>>((float*)d_out, (const float4*)W2, b2, E);
}